// round 8
// baseline (speedup 1.0000x reference)
#include <cuda_runtime.h>
#include <cuda_bf16.h>

// ---------------------------------------------------------------------------
// DiffJPEG: out = x + (jpeg75(clip(x,0,1)) - x), x: [16,3,512,512] fp32
// Fully fused single kernel. CTA = 32x32 pixel tile, 256 threads.
// ---------------------------------------------------------------------------

// DCT-II matrix D[u][x] = 0.5*cos((2x+1)u*pi/16), row 0 scaled by 1/sqrt(2).
__constant__ float cD[64] = {
    0.3535533906f,  0.3535533906f,  0.3535533906f,  0.3535533906f,
    0.3535533906f,  0.3535533906f,  0.3535533906f,  0.3535533906f,
    0.4903926402f,  0.4157348062f,  0.2777851165f,  0.0975451610f,
   -0.0975451610f, -0.2777851165f, -0.4157348062f, -0.4903926402f,
    0.4619397663f,  0.1913417162f, -0.1913417162f, -0.4619397663f,
   -0.4619397663f, -0.1913417162f,  0.1913417162f,  0.4619397663f,
    0.4157348062f, -0.0975451610f, -0.4903926402f, -0.2777851165f,
    0.2777851165f,  0.4903926402f,  0.0975451610f, -0.4157348062f,
    0.3535533906f, -0.3535533906f, -0.3535533906f,  0.3535533906f,
    0.3535533906f, -0.3535533906f, -0.3535533906f,  0.3535533906f,
    0.2777851165f, -0.4903926402f,  0.0975451610f,  0.4157348062f,
   -0.4157348062f, -0.0975451610f,  0.4903926402f, -0.2777851165f,
    0.1913417162f, -0.4619397663f,  0.4619397663f, -0.1913417162f,
   -0.1913417162f,  0.4619397663f, -0.4619397663f,  0.1913417162f,
    0.0975451610f, -0.2777851165f,  0.4157348062f, -0.4903926402f,
    0.4903926402f, -0.4157348062f,  0.2777851165f, -0.0975451610f
};

// Quant tables pre-multiplied by factor = (200 - 2*75)/100 = 0.5 (exact in fp32)
__constant__ float cQY[64] = {
     8.0f,  5.5f,  5.0f,  8.0f, 12.0f, 20.0f, 25.5f, 30.5f,
     6.0f,  6.0f,  7.0f,  9.5f, 13.0f, 29.0f, 30.0f, 27.5f,
     7.0f,  6.5f,  8.0f, 12.0f, 20.0f, 28.5f, 34.5f, 28.0f,
     7.0f,  8.5f, 11.0f, 14.5f, 25.5f, 43.5f, 40.0f, 31.0f,
     9.0f, 11.0f, 18.5f, 28.0f, 34.0f, 54.5f, 51.5f, 38.5f,
    12.0f, 17.5f, 27.5f, 32.0f, 40.5f, 52.0f, 56.5f, 46.0f,
    24.5f, 32.0f, 39.0f, 43.5f, 51.5f, 60.5f, 60.0f, 50.5f,
    36.0f, 46.0f, 47.5f, 49.0f, 56.0f, 50.0f, 51.5f, 49.5f
};
__constant__ float cQC[64] = {
     8.5f,  9.0f, 12.0f, 23.5f, 49.5f, 49.5f, 49.5f, 49.5f,
     9.0f, 10.5f, 13.0f, 33.0f, 49.5f, 49.5f, 49.5f, 49.5f,
    12.0f, 13.0f, 28.0f, 49.5f, 49.5f, 49.5f, 49.5f, 49.5f,
    23.5f, 33.0f, 49.5f, 49.5f, 49.5f, 49.5f, 49.5f, 49.5f,
    49.5f, 49.5f, 49.5f, 49.5f, 49.5f, 49.5f, 49.5f, 49.5f,
    49.5f, 49.5f, 49.5f, 49.5f, 49.5f, 49.5f, 49.5f, 49.5f,
    49.5f, 49.5f, 49.5f, 49.5f, 49.5f, 49.5f, 49.5f, 49.5f,
    49.5f, 49.5f, 49.5f, 49.5f, 49.5f, 49.5f, 49.5f, 49.5f
};

#define IMG 512

__global__ void __launch_bounds__(256, 4)
diffjpeg_kernel(const float* __restrict__ in, float* __restrict__ out)
{
    __shared__ float sy [32][33];
    __shared__ float scb[32][33];
    __shared__ float scr[32][33];
    __shared__ float st [24][8][9];   // transpose buffer (T, then S)
    __shared__ float scbr[16][17];    // reconstructed subsampled Cb
    __shared__ float scrr[16][17];    // reconstructed subsampled Cr

    const int t    = threadIdx.x;
    const int row  = t >> 3;          // 0..31
    const int col0 = (t & 7) << 2;    // 0,4,...,28

    const int b  = blockIdx.z;
    const int gy = blockIdx.y * 32 + row;
    const int gx = blockIdx.x * 32 + col0;

    const size_t plane = (size_t)IMG * IMG;
    const size_t base  = ((size_t)b * 3) * plane + (size_t)gy * IMG + gx;

    // ---------- Phase A: load, clip, *255, RGB->YCbCr ----------
    const float4 xr4 = *(const float4*)(in + base);
    const float4 xg4 = *(const float4*)(in + base + plane);
    const float4 xb4 = *(const float4*)(in + base + 2 * plane);

    float xr[4] = {xr4.x, xr4.y, xr4.z, xr4.w};
    float xg[4] = {xg4.x, xg4.y, xg4.z, xg4.w};
    float xb[4] = {xb4.x, xb4.y, xb4.z, xb4.w};

    #pragma unroll
    for (int i = 0; i < 4; i++) {
        float R = fminf(fmaxf(xr[i], 0.f), 1.f) * 255.f;
        float G = fminf(fmaxf(xg[i], 0.f), 1.f) * 255.f;
        float B = fminf(fmaxf(xb[i], 0.f), 1.f) * 255.f;
        float Y  =  0.299f    * R + 0.587f    * G + 0.114f    * B;
        float CB = -0.168736f * R - 0.331264f * G + 0.5f      * B + 128.f;
        float CR =  0.5f      * R - 0.418688f * G - 0.081312f * B + 128.f;
        sy [row][col0 + i] = Y;
        scb[row][col0 + i] = CB;
        scr[row][col0 + i] = CR;
    }
    __syncthreads();

    // 24 blocks: 0..15 Y (4x4 grid), 16..19 Cb (2x2), 20..23 Cr (2x2)
    const int bi = t >> 3;      // block id (valid for t < 192)
    const int r  = t & 7;       // row within block
    const bool active = (t < 192);

    int br = 0, bc = 0;         // write-back coords
    float srec[8];

    if (active) {
        // ---------- Phase B: row DCT  T[r][v] = sum_c X[r][c]*D[v][c] ----
        float xrow[8];
        if (bi < 16) {
            br = (bi >> 2) * 8 + r;
            bc = (bi & 3) * 8;
            #pragma unroll
            for (int c = 0; c < 8; c++) xrow[c] = sy[br][bc + c] - 128.f;
        } else {
            const int cj = (bi < 20) ? (bi - 16) : (bi - 20);
            const float (*sc)[33] = (bi < 20) ? scb : scr;
            br = (cj >> 1) * 8 + r;      // subsampled row
            bc = (cj & 1) * 8;           // subsampled col base
            const int R2 = br * 2;
            #pragma unroll
            for (int c = 0; c < 8; c++) {
                int cc = (bc + c) * 2;
                xrow[c] = 0.25f * (sc[R2][cc] + sc[R2][cc + 1] +
                                   sc[R2 + 1][cc] + sc[R2 + 1][cc + 1]) - 128.f;
            }
        }
        #pragma unroll
        for (int v = 0; v < 8; v++) {
            float a = 0.f;
            #pragma unroll
            for (int c = 0; c < 8; c++) a += xrow[c] * cD[v * 8 + c];
            st[bi][r][v] = a;
        }
    }
    __syncthreads();

    if (active) {
        // ---------- Phase C: column DCT + quantize + half inverse ----
        const int u = r;
        const float* q = (bi < 16) ? cQY : cQC;
        float k[8];
        #pragma unroll
        for (int v = 0; v < 8; v++) {
            float a = 0.f;
            #pragma unroll
            for (int x = 0; x < 8; x++) a += cD[u * 8 + x] * st[bi][x][v];
            float qq = q[u * 8 + v];
            k[v] = rintf(a / qq) * qq;            // round-half-even, true div
        }
        // S[u][y] = sum_v K[u][v] * D[v][y]
        #pragma unroll
        for (int y = 0; y < 8; y++) {
            float a = 0.f;
            #pragma unroll
            for (int v = 0; v < 8; v++) a += k[v] * cD[v * 8 + y];
            srec[y] = a;
        }
    }
    __syncthreads();            // all T reads done before overwrite

    if (active) {
        #pragma unroll
        for (int y = 0; y < 8; y++) st[bi][r][y] = srec[y];
    }
    __syncthreads();

    if (active) {
        // ---------- Phase D: rec[r][y] = sum_u D[u][r]*S[u][y] + 128 ----
        #pragma unroll
        for (int y = 0; y < 8; y++) {
            float a = 0.f;
            #pragma unroll
            for (int u2 = 0; u2 < 8; u2++) a += cD[u2 * 8 + r] * st[bi][u2][y];
            a += 128.f;
            if (bi < 16)       sy  [br][bc + y] = a;
            else if (bi < 20)  scbr[br][bc + y] = a;
            else               scrr[br][bc + y] = a;
        }
    }
    __syncthreads();

    // ---------- Phase E: upsample chroma, YCbCr->RGB, clip, emit ----------
    float or_[4], og_[4], ob_[4];
    #pragma unroll
    for (int i = 0; i < 4; i++) {
        int cc = col0 + i;
        float Y   = sy[row][cc];
        float cbm = scbr[row >> 1][cc >> 1] - 128.f;
        float crm = scrr[row >> 1][cc >> 1] - 128.f;
        float R2 = Y + 1.402f * crm;
        float G2 = Y - 0.344136f * cbm - 0.714136f * crm;
        float B2 = Y + 1.772f * cbm;
        R2 = fminf(fmaxf(R2, 0.f), 255.f) * (1.f / 255.f);
        G2 = fminf(fmaxf(G2, 0.f), 255.f) * (1.f / 255.f);
        B2 = fminf(fmaxf(B2, 0.f), 255.f) * (1.f / 255.f);
        // out = x + (jpeg - x), matching the reference's fp32 arithmetic
        or_[i] = xr[i] + (R2 - xr[i]);
        og_[i] = xg[i] + (G2 - xg[i]);
        ob_[i] = xb[i] + (B2 - xb[i]);
    }
    *(float4*)(out + base)             = make_float4(or_[0], or_[1], or_[2], or_[3]);
    *(float4*)(out + base + plane)     = make_float4(og_[0], og_[1], og_[2], og_[3]);
    *(float4*)(out + base + 2 * plane) = make_float4(ob_[0], ob_[1], ob_[2], ob_[3]);
}

extern "C" void kernel_launch(void* const* d_in, const int* in_sizes, int n_in,
                              void* d_out, int out_size)
{
    const float* x = (const float*)d_in[0];
    float* out = (float*)d_out;
    dim3 grid(IMG / 32, IMG / 32, 16);   // (16,16,16) = 4096 CTAs
    diffjpeg_kernel<<<grid, 256>>>(x, out);
}

// round 9
// speedup vs baseline: 1.0921x; 1.0921x over previous
#include <cuda_runtime.h>
#include <cuda_bf16.h>

// ---------------------------------------------------------------------------
// DiffJPEG: out = x + (jpeg75(clip(x,0,1)) - x), x: [16,3,512,512] fp32
// Fused single kernel. CTA = 32x32 pixel tile, 256 threads, 5 CTAs/SM.
// R9: smem tables (stride 9, conflict-free for lane-varying u),
//     st2 double buffer (4 barriers), x re-load in epilogue (fewer regs).
// ---------------------------------------------------------------------------

// DCT-II matrix D[u][x] = 0.5*cos((2x+1)u*pi/16), row 0 scaled by 1/sqrt(2).
__constant__ float cD[64] = {
    0.3535533906f,  0.3535533906f,  0.3535533906f,  0.3535533906f,
    0.3535533906f,  0.3535533906f,  0.3535533906f,  0.3535533906f,
    0.4903926402f,  0.4157348062f,  0.2777851165f,  0.0975451610f,
   -0.0975451610f, -0.2777851165f, -0.4157348062f, -0.4903926402f,
    0.4619397663f,  0.1913417162f, -0.1913417162f, -0.4619397663f,
   -0.4619397663f, -0.1913417162f,  0.1913417162f,  0.4619397663f,
    0.4157348062f, -0.0975451610f, -0.4903926402f, -0.2777851165f,
    0.2777851165f,  0.4903926402f,  0.0975451610f, -0.4157348062f,
    0.3535533906f, -0.3535533906f, -0.3535533906f,  0.3535533906f,
    0.3535533906f, -0.3535533906f, -0.3535533906f,  0.3535533906f,
    0.2777851165f, -0.4903926402f,  0.0975451610f,  0.4157348062f,
   -0.4157348062f, -0.0975451610f,  0.4903926402f, -0.2777851165f,
    0.1913417162f, -0.4619397663f,  0.4619397663f, -0.1913417162f,
   -0.1913417162f,  0.4619397663f, -0.4619397663f,  0.1913417162f,
    0.0975451610f, -0.2777851165f,  0.4157348062f, -0.4903926402f,
    0.4903926402f, -0.4157348062f,  0.2777851165f, -0.0975451610f
};

// Quant tables pre-multiplied by factor = (200 - 2*75)/100 = 0.5 (exact in fp32)
__constant__ float cQY[64] = {
     8.0f,  5.5f,  5.0f,  8.0f, 12.0f, 20.0f, 25.5f, 30.5f,
     6.0f,  6.0f,  7.0f,  9.5f, 13.0f, 29.0f, 30.0f, 27.5f,
     7.0f,  6.5f,  8.0f, 12.0f, 20.0f, 28.5f, 34.5f, 28.0f,
     7.0f,  8.5f, 11.0f, 14.5f, 25.5f, 43.5f, 40.0f, 31.0f,
     9.0f, 11.0f, 18.5f, 28.0f, 34.0f, 54.5f, 51.5f, 38.5f,
    12.0f, 17.5f, 27.5f, 32.0f, 40.5f, 52.0f, 56.5f, 46.0f,
    24.5f, 32.0f, 39.0f, 43.5f, 51.5f, 60.5f, 60.0f, 50.5f,
    36.0f, 46.0f, 47.5f, 49.0f, 56.0f, 50.0f, 51.5f, 49.5f
};
__constant__ float cQC[64] = {
     8.5f,  9.0f, 12.0f, 23.5f, 49.5f, 49.5f, 49.5f, 49.5f,
     9.0f, 10.5f, 13.0f, 33.0f, 49.5f, 49.5f, 49.5f, 49.5f,
    12.0f, 13.0f, 28.0f, 49.5f, 49.5f, 49.5f, 49.5f, 49.5f,
    23.5f, 33.0f, 49.5f, 49.5f, 49.5f, 49.5f, 49.5f, 49.5f,
    49.5f, 49.5f, 49.5f, 49.5f, 49.5f, 49.5f, 49.5f, 49.5f,
    49.5f, 49.5f, 49.5f, 49.5f, 49.5f, 49.5f, 49.5f, 49.5f,
    49.5f, 49.5f, 49.5f, 49.5f, 49.5f, 49.5f, 49.5f, 49.5f,
    49.5f, 49.5f, 49.5f, 49.5f, 49.5f, 49.5f, 49.5f, 49.5f
};

#define IMG 512

__global__ void __launch_bounds__(256, 5)
diffjpeg_kernel(const float* __restrict__ in, float* __restrict__ out)
{
    __shared__ float sy  [32][33];
    __shared__ float scb [32][33];
    __shared__ float scr [32][33];
    __shared__ float st  [24][8][9];   // forward-transpose buffer T
    __shared__ float st2 [24][8][9];   // reconstructed-coef buffer S
    __shared__ float scbr[16][17];     // reconstructed subsampled Cb
    __shared__ float scrr[16][17];     // reconstructed subsampled Cr
    __shared__ float sD  [72];         // DCT matrix, stride 9 (conflict-free)
    __shared__ float sQY [72];         // quant Y, stride 9
    __shared__ float sQC [72];         // quant C, stride 9

    const int t    = threadIdx.x;
    const int row  = t >> 3;          // 0..31
    const int col0 = (t & 7) << 2;    // 0,4,...,28

    const int b  = blockIdx.z;
    const int gy = blockIdx.y * 32 + row;
    const int gx = blockIdx.x * 32 + col0;

    const size_t plane = (size_t)IMG * IMG;
    const size_t base  = ((size_t)b * 3) * plane + (size_t)gy * IMG + gx;

    // ---------- Table copy to shared (stride 9) ----------
    if (t < 192) {
        int tab = t >> 6;             // 0: D, 1: QY, 2: QC
        int e   = t & 63;
        int dst = (e >> 3) * 9 + (e & 7);
        float v = (tab == 0) ? cD[e] : (tab == 1) ? cQY[e] : cQC[e];
        if (tab == 0)      sD [dst] = v;
        else if (tab == 1) sQY[dst] = v;
        else               sQC[dst] = v;
    }

    // ---------- Phase A: load, clip, *255, RGB->YCbCr ----------
    {
        const float4 xr4 = *(const float4*)(in + base);
        const float4 xg4 = *(const float4*)(in + base + plane);
        const float4 xb4 = *(const float4*)(in + base + 2 * plane);
        float xr[4] = {xr4.x, xr4.y, xr4.z, xr4.w};
        float xg[4] = {xg4.x, xg4.y, xg4.z, xg4.w};
        float xb[4] = {xb4.x, xb4.y, xb4.z, xb4.w};
        #pragma unroll
        for (int i = 0; i < 4; i++) {
            float R = fminf(fmaxf(xr[i], 0.f), 1.f) * 255.f;
            float G = fminf(fmaxf(xg[i], 0.f), 1.f) * 255.f;
            float B = fminf(fmaxf(xb[i], 0.f), 1.f) * 255.f;
            float Y  =  0.299f    * R + 0.587f    * G + 0.114f    * B;
            float CB = -0.168736f * R - 0.331264f * G + 0.5f      * B + 128.f;
            float CR =  0.5f      * R - 0.418688f * G - 0.081312f * B + 128.f;
            sy [row][col0 + i] = Y;
            scb[row][col0 + i] = CB;
            scr[row][col0 + i] = CR;
        }
    }
    __syncthreads();

    // 24 blocks: 0..15 Y (4x4 grid), 16..19 Cb (2x2), 20..23 Cr (2x2)
    const int bi = t >> 3;      // block id (valid for t < 192)
    const int r  = t & 7;       // row within block
    const bool active = (t < 192);

    int br = 0, bc = 0;         // write-back coords

    if (active) {
        // ---------- Phase B: row DCT  T[r][v] = sum_c X[r][c]*D[v][c] ----
        float xrow[8];
        if (bi < 16) {
            br = (bi >> 2) * 8 + r;
            bc = (bi & 3) * 8;
            #pragma unroll
            for (int c = 0; c < 8; c++) xrow[c] = sy[br][bc + c] - 128.f;
        } else {
            const int cj = (bi < 20) ? (bi - 16) : (bi - 20);
            const float (*sc)[33] = (bi < 20) ? scb : scr;
            br = (cj >> 1) * 8 + r;      // subsampled row
            bc = (cj & 1) * 8;           // subsampled col base
            const int R2 = br * 2;
            #pragma unroll
            for (int c = 0; c < 8; c++) {
                int cc = (bc + c) * 2;
                xrow[c] = 0.25f * (sc[R2][cc] + sc[R2][cc + 1] +
                                   sc[R2 + 1][cc] + sc[R2 + 1][cc + 1]) - 128.f;
            }
        }
        #pragma unroll
        for (int v = 0; v < 8; v++) {
            float a = 0.f;
            #pragma unroll
            for (int c = 0; c < 8; c++) a += xrow[c] * sD[v * 9 + c];
            st[bi][r][v] = a;
        }
    }
    __syncthreads();

    if (active) {
        // ---------- Phase C: column DCT + quantize + half inverse ----
        const int u = r;
        const float* qs = (bi < 16) ? sQY : sQC;
        float k[8];
        #pragma unroll
        for (int v = 0; v < 8; v++) {
            float a = 0.f;
            #pragma unroll
            for (int x = 0; x < 8; x++) a += sD[u * 9 + x] * st[bi][x][v];
            float qq = qs[u * 9 + v];
            k[v] = rintf(a / qq) * qq;            // round-half-even, true div
        }
        // S[u][y] = sum_v K[u][v] * D[v][y]  -> st2 (no WAR barrier needed)
        #pragma unroll
        for (int y = 0; y < 8; y++) {
            float a = 0.f;
            #pragma unroll
            for (int v = 0; v < 8; v++) a += k[v] * sD[v * 9 + y];
            st2[bi][r][y] = a;
        }
    }
    __syncthreads();

    if (active) {
        // ---------- Phase D: rec[r][y] = sum_u D[u][r]*S[u][y] + 128 ----
        #pragma unroll
        for (int y = 0; y < 8; y++) {
            float a = 0.f;
            #pragma unroll
            for (int u2 = 0; u2 < 8; u2++) a += sD[u2 * 9 + r] * st2[bi][u2][y];
            a += 128.f;
            if (bi < 16)       sy  [br][bc + y] = a;
            else if (bi < 20)  scbr[br][bc + y] = a;
            else               scrr[br][bc + y] = a;
        }
    }
    __syncthreads();

    // ---------- Phase E: upsample chroma, YCbCr->RGB, clip, emit ----------
    // Re-load x (L1-resident from Phase A) instead of carrying 12 registers.
    {
        const float4 xr4 = *(const float4*)(in + base);
        const float4 xg4 = *(const float4*)(in + base + plane);
        const float4 xb4 = *(const float4*)(in + base + 2 * plane);
        const float xr[4] = {xr4.x, xr4.y, xr4.z, xr4.w};
        const float xg[4] = {xg4.x, xg4.y, xg4.z, xg4.w};
        const float xb[4] = {xb4.x, xb4.y, xb4.z, xb4.w};

        float or_[4], og_[4], ob_[4];
        #pragma unroll
        for (int i = 0; i < 4; i++) {
            int cc = col0 + i;
            float Y   = sy[row][cc];
            float cbm = scbr[row >> 1][cc >> 1] - 128.f;
            float crm = scrr[row >> 1][cc >> 1] - 128.f;
            float R2 = Y + 1.402f * crm;
            float G2 = Y - 0.344136f * cbm - 0.714136f * crm;
            float B2 = Y + 1.772f * cbm;
            R2 = fminf(fmaxf(R2, 0.f), 255.f) * (1.f / 255.f);
            G2 = fminf(fmaxf(G2, 0.f), 255.f) * (1.f / 255.f);
            B2 = fminf(fmaxf(B2, 0.f), 255.f) * (1.f / 255.f);
            // out = x + (jpeg - x), matching the reference's fp32 arithmetic
            or_[i] = xr[i] + (R2 - xr[i]);
            og_[i] = xg[i] + (G2 - xg[i]);
            ob_[i] = xb[i] + (B2 - xb[i]);
        }
        *(float4*)(out + base)             = make_float4(or_[0], or_[1], or_[2], or_[3]);
        *(float4*)(out + base + plane)     = make_float4(og_[0], og_[1], og_[2], og_[3]);
        *(float4*)(out + base + 2 * plane) = make_float4(ob_[0], ob_[1], ob_[2], ob_[3]);
    }
}

extern "C" void kernel_launch(void* const* d_in, const int* in_sizes, int n_in,
                              void* d_out, int out_size)
{
    const float* x = (const float*)d_in[0];
    float* out = (float*)d_out;
    dim3 grid(IMG / 32, IMG / 32, 16);   // (16,16,16) = 4096 CTAs
    diffjpeg_kernel<<<grid, 256>>>(x, out);
}

// round 12
// speedup vs baseline: 1.2246x; 1.1213x over previous
#include <cuda_runtime.h>
#include <cuda_bf16.h>

// ---------------------------------------------------------------------------
// DiffJPEG: out = x + (jpeg75(clip(x,0,1)) - x), x: [16,3,512,512] fp32
// Fused single kernel. CTA = 32x32 pixel tile, 256 threads, 5 CTAs/SM.
// R10: float4 smem paths in the DCT matmuls (LDS.128/STS.128), const-mem
//      tables for warp-uniform reads, smem tables only for lane-varying u.
// ---------------------------------------------------------------------------

// DCT-II matrix D[u][x] = 0.5*cos((2x+1)u*pi/16), row 0 scaled by 1/sqrt(2).
__constant__ float cD[64] = {
    0.3535533906f,  0.3535533906f,  0.3535533906f,  0.3535533906f,
    0.3535533906f,  0.3535533906f,  0.3535533906f,  0.3535533906f,
    0.4903926402f,  0.4157348062f,  0.2777851165f,  0.0975451610f,
   -0.0975451610f, -0.2777851165f, -0.4157348062f, -0.4903926402f,
    0.4619397663f,  0.1913417162f, -0.1913417162f, -0.4619397663f,
   -0.4619397663f, -0.1913417162f,  0.1913417162f,  0.4619397663f,
    0.4157348062f, -0.0975451610f, -0.4903926402f, -0.2777851165f,
    0.2777851165f,  0.4903926402f,  0.0975451610f, -0.4157348062f,
    0.3535533906f, -0.3535533906f, -0.3535533906f,  0.3535533906f,
    0.3535533906f, -0.3535533906f, -0.3535533906f,  0.3535533906f,
    0.2777851165f, -0.4903926402f,  0.0975451610f,  0.4157348062f,
   -0.4157348062f, -0.0975451610f,  0.4903926402f, -0.2777851165f,
    0.1913417162f, -0.4619397663f,  0.4619397663f, -0.1913417162f,
   -0.1913417162f,  0.4619397663f, -0.4619397663f,  0.1913417162f,
    0.0975451610f, -0.2777851165f,  0.4157348062f, -0.4903926402f,
    0.4903926402f, -0.4157348062f,  0.2777851165f, -0.0975451610f
};

// Quant tables pre-multiplied by factor = (200 - 2*75)/100 = 0.5 (exact in fp32)
__constant__ float cQY[64] = {
     8.0f,  5.5f,  5.0f,  8.0f, 12.0f, 20.0f, 25.5f, 30.5f,
     6.0f,  6.0f,  7.0f,  9.5f, 13.0f, 29.0f, 30.0f, 27.5f,
     7.0f,  6.5f,  8.0f, 12.0f, 20.0f, 28.5f, 34.5f, 28.0f,
     7.0f,  8.5f, 11.0f, 14.5f, 25.5f, 43.5f, 40.0f, 31.0f,
     9.0f, 11.0f, 18.5f, 28.0f, 34.0f, 54.5f, 51.5f, 38.5f,
    12.0f, 17.5f, 27.5f, 32.0f, 40.5f, 52.0f, 56.5f, 46.0f,
    24.5f, 32.0f, 39.0f, 43.5f, 51.5f, 60.5f, 60.0f, 50.5f,
    36.0f, 46.0f, 47.5f, 49.0f, 56.0f, 50.0f, 51.5f, 49.5f
};
__constant__ float cQC[64] = {
     8.5f,  9.0f, 12.0f, 23.5f, 49.5f, 49.5f, 49.5f, 49.5f,
     9.0f, 10.5f, 13.0f, 33.0f, 49.5f, 49.5f, 49.5f, 49.5f,
    12.0f, 13.0f, 28.0f, 49.5f, 49.5f, 49.5f, 49.5f, 49.5f,
    23.5f, 33.0f, 49.5f, 49.5f, 49.5f, 49.5f, 49.5f, 49.5f,
    49.5f, 49.5f, 49.5f, 49.5f, 49.5f, 49.5f, 49.5f, 49.5f,
    49.5f, 49.5f, 49.5f, 49.5f, 49.5f, 49.5f, 49.5f, 49.5f,
    49.5f, 49.5f, 49.5f, 49.5f, 49.5f, 49.5f, 49.5f, 49.5f,
    49.5f, 49.5f, 49.5f, 49.5f, 49.5f, 49.5f, 49.5f, 49.5f
};

#define IMG 512

__global__ void __launch_bounds__(256, 5)
diffjpeg_kernel(const float* __restrict__ in, float* __restrict__ out)
{
    // Strides chosen so 8-float rows are 16B-aligned (stride % 4 == 0)
    __shared__ __align__(16) float sy  [32][36];
    __shared__ __align__(16) float scb [32][36];
    __shared__ __align__(16) float scr [32][36];
    __shared__ __align__(16) float st  [24][8][8];  // forward-transpose buffer T
    __shared__ __align__(16) float st2 [24][8][8];  // reconstructed-coef buffer S
    __shared__ __align__(16) float scbr[16][20];    // reconstructed subsampled Cb
    __shared__ __align__(16) float scrr[16][20];    // reconstructed subsampled Cr
    __shared__ float sD  [72];   // DCT matrix, stride 9 (lane-varying u reads)
    __shared__ float sQY [72];   // quant Y, stride 9
    __shared__ float sQC [72];   // quant C, stride 9

    const int t    = threadIdx.x;
    const int row  = t >> 3;          // 0..31
    const int col0 = (t & 7) << 2;    // 0,4,...,28

    const int b  = blockIdx.z;
    const int gy = blockIdx.y * 32 + row;
    const int gx = blockIdx.x * 32 + col0;

    const size_t plane = (size_t)IMG * IMG;
    const size_t base  = ((size_t)b * 3) * plane + (size_t)gy * IMG + gx;

    // ---------- Table copy to shared (stride 9) ----------
    if (t < 192) {
        int tab = t >> 6;             // 0: D, 1: QY, 2: QC
        int e   = t & 63;
        int dst = (e >> 3) * 9 + (e & 7);
        float v = (tab == 0) ? cD[e] : (tab == 1) ? cQY[e] : cQC[e];
        if (tab == 0)      sD [dst] = v;
        else if (tab == 1) sQY[dst] = v;
        else               sQC[dst] = v;
    }

    // ---------- Phase A: load, clip, *255, RGB->YCbCr ----------
    {
        const float4 xr4 = *(const float4*)(in + base);
        const float4 xg4 = *(const float4*)(in + base + plane);
        const float4 xb4 = *(const float4*)(in + base + 2 * plane);
        float xr[4] = {xr4.x, xr4.y, xr4.z, xr4.w};
        float xg[4] = {xg4.x, xg4.y, xg4.z, xg4.w};
        float xb[4] = {xb4.x, xb4.y, xb4.z, xb4.w};
        float ya[4], cba[4], cra[4];
        #pragma unroll
        for (int i = 0; i < 4; i++) {
            float R = fminf(fmaxf(xr[i], 0.f), 1.f) * 255.f;
            float G = fminf(fmaxf(xg[i], 0.f), 1.f) * 255.f;
            float B = fminf(fmaxf(xb[i], 0.f), 1.f) * 255.f;
            ya [i] =  0.299f    * R + 0.587f    * G + 0.114f    * B;
            cba[i] = -0.168736f * R - 0.331264f * G + 0.5f      * B + 128.f;
            cra[i] =  0.5f      * R - 0.418688f * G - 0.081312f * B + 128.f;
        }
        *(float4*)&sy [row][col0] = make_float4(ya [0], ya [1], ya [2], ya [3]);
        *(float4*)&scb[row][col0] = make_float4(cba[0], cba[1], cba[2], cba[3]);
        *(float4*)&scr[row][col0] = make_float4(cra[0], cra[1], cra[2], cra[3]);
    }
    __syncthreads();

    // 24 blocks: 0..15 Y (4x4 grid), 16..19 Cb (2x2), 20..23 Cr (2x2)
    const int bi = t >> 3;      // block id (valid for t < 192)
    const int r  = t & 7;       // row within block
    const bool active = (t < 192);

    int br = 0, bc = 0;         // write-back coords

    if (active) {
        // ---------- Phase B: row DCT  T[r][v] = sum_c X[r][c]*D[v][c] ----
        float xrow[8];
        if (bi < 16) {
            br = (bi >> 2) * 8 + r;
            bc = (bi & 3) * 8;
            const float4 lo = *(const float4*)&sy[br][bc];
            const float4 hi = *(const float4*)&sy[br][bc + 4];
            xrow[0] = lo.x - 128.f; xrow[1] = lo.y - 128.f;
            xrow[2] = lo.z - 128.f; xrow[3] = lo.w - 128.f;
            xrow[4] = hi.x - 128.f; xrow[5] = hi.y - 128.f;
            xrow[6] = hi.z - 128.f; xrow[7] = hi.w - 128.f;
        } else {
            const int cj = (bi < 20) ? (bi - 16) : (bi - 20);
            const float (*sc)[36] = (bi < 20) ? scb : scr;
            br = (cj >> 1) * 8 + r;      // subsampled row
            bc = (cj & 1) * 8;           // subsampled col base
            const int R2 = br * 2;
            #pragma unroll
            for (int c = 0; c < 8; c++) {
                int cc = (bc + c) * 2;
                xrow[c] = 0.25f * (sc[R2][cc] + sc[R2][cc + 1] +
                                   sc[R2 + 1][cc] + sc[R2 + 1][cc + 1]) - 128.f;
            }
        }
        float trow[8];
        #pragma unroll
        for (int v = 0; v < 8; v++) {
            float a = 0.f;
            #pragma unroll
            for (int c = 0; c < 8; c++) a += xrow[c] * cD[v * 8 + c];  // uniform -> LDC
            trow[v] = a;
        }
        *(float4*)&st[bi][r][0] = make_float4(trow[0], trow[1], trow[2], trow[3]);
        *(float4*)&st[bi][r][4] = make_float4(trow[4], trow[5], trow[6], trow[7]);
    }
    __syncthreads();

    if (active) {
        // ---------- Phase C: column DCT + quantize + half inverse ----
        const int u = r;
        // lane-varying row of D (conflict-free stride-9 smem)
        float dU[8];
        #pragma unroll
        for (int x = 0; x < 8; x++) dU[x] = sD[u * 9 + x];

        // K[u][v] = sum_x D[u][x] * T[x][v], x-outer, float4 row loads
        float k[8] = {0.f, 0.f, 0.f, 0.f, 0.f, 0.f, 0.f, 0.f};
        #pragma unroll
        for (int x = 0; x < 8; x++) {
            const float4 lo = *(const float4*)&st[bi][x][0];
            const float4 hi = *(const float4*)&st[bi][x][4];
            const float d = dU[x];
            k[0] += d * lo.x; k[1] += d * lo.y; k[2] += d * lo.z; k[3] += d * lo.w;
            k[4] += d * hi.x; k[5] += d * hi.y; k[6] += d * hi.z; k[7] += d * hi.w;
        }
        const float* qs = (bi < 16) ? sQY : sQC;
        #pragma unroll
        for (int v = 0; v < 8; v++) {
            float qq = qs[u * 9 + v];
            k[v] = rintf(k[v] / qq) * qq;         // round-half-even, true div
        }
        // S[u][y] = sum_v K[u][v] * D[v][y]  (uniform D -> LDC)
        float srow[8];
        #pragma unroll
        for (int y = 0; y < 8; y++) {
            float a = 0.f;
            #pragma unroll
            for (int v = 0; v < 8; v++) a += k[v] * cD[v * 8 + y];
            srow[y] = a;
        }
        *(float4*)&st2[bi][r][0] = make_float4(srow[0], srow[1], srow[2], srow[3]);
        *(float4*)&st2[bi][r][4] = make_float4(srow[4], srow[5], srow[6], srow[7]);
    }
    __syncthreads();

    if (active) {
        // ---------- Phase D: rec[r][y] = sum_u D[u][r]*S[u][y] + 128 ----
        float rec[8] = {0.f, 0.f, 0.f, 0.f, 0.f, 0.f, 0.f, 0.f};
        #pragma unroll
        for (int u2 = 0; u2 < 8; u2++) {
            const float d = sD[u2 * 9 + r];       // lane-varying, conflict-free
            const float4 lo = *(const float4*)&st2[bi][u2][0];
            const float4 hi = *(const float4*)&st2[bi][u2][4];
            rec[0] += d * lo.x; rec[1] += d * lo.y; rec[2] += d * lo.z; rec[3] += d * lo.w;
            rec[4] += d * hi.x; rec[5] += d * hi.y; rec[6] += d * hi.z; rec[7] += d * hi.w;
        }
        #pragma unroll
        for (int y = 0; y < 8; y++) rec[y] += 128.f;
        if (bi < 16) {
            *(float4*)&sy[br][bc]     = make_float4(rec[0], rec[1], rec[2], rec[3]);
            *(float4*)&sy[br][bc + 4] = make_float4(rec[4], rec[5], rec[6], rec[7]);
        } else if (bi < 20) {
            *(float4*)&scbr[br][bc]     = make_float4(rec[0], rec[1], rec[2], rec[3]);
            *(float4*)&scbr[br][bc + 4] = make_float4(rec[4], rec[5], rec[6], rec[7]);
        } else {
            *(float4*)&scrr[br][bc]     = make_float4(rec[0], rec[1], rec[2], rec[3]);
            *(float4*)&scrr[br][bc + 4] = make_float4(rec[4], rec[5], rec[6], rec[7]);
        }
    }
    __syncthreads();

    // ---------- Phase E: upsample chroma, YCbCr->RGB, clip, emit ----------
    // Re-load x (L1-resident from Phase A) instead of carrying 12 registers.
    {
        const float4 xr4 = *(const float4*)(in + base);
        const float4 xg4 = *(const float4*)(in + base + plane);
        const float4 xb4 = *(const float4*)(in + base + 2 * plane);
        const float xr[4] = {xr4.x, xr4.y, xr4.z, xr4.w};
        const float xg[4] = {xg4.x, xg4.y, xg4.z, xg4.w};
        const float xb[4] = {xb4.x, xb4.y, xb4.z, xb4.w};

        const float4 y4 = *(const float4*)&sy[row][col0];
        const float yv[4] = {y4.x, y4.y, y4.z, y4.w};

        float or_[4], og_[4], ob_[4];
        #pragma unroll
        for (int i = 0; i < 4; i++) {
            int cc = col0 + i;
            float Y   = yv[i];
            float cbm = scbr[row >> 1][cc >> 1] - 128.f;
            float crm = scrr[row >> 1][cc >> 1] - 128.f;
            float R2 = Y + 1.402f * crm;
            float G2 = Y - 0.344136f * cbm - 0.714136f * crm;
            float B2 = Y + 1.772f * cbm;
            R2 = fminf(fmaxf(R2, 0.f), 255.f) * (1.f / 255.f);
            G2 = fminf(fmaxf(G2, 0.f), 255.f) * (1.f / 255.f);
            B2 = fminf(fmaxf(B2, 0.f), 255.f) * (1.f / 255.f);
            // out = x + (jpeg - x), matching the reference's fp32 arithmetic
            or_[i] = xr[i] + (R2 - xr[i]);
            og_[i] = xg[i] + (G2 - xg[i]);
            ob_[i] = xb[i] + (B2 - xb[i]);
        }
        *(float4*)(out + base)             = make_float4(or_[0], or_[1], or_[2], or_[3]);
        *(float4*)(out + base + plane)     = make_float4(og_[0], og_[1], og_[2], og_[3]);
        *(float4*)(out + base + 2 * plane) = make_float4(ob_[0], ob_[1], ob_[2], ob_[3]);
    }
}

extern "C" void kernel_launch(void* const* d_in, const int* in_sizes, int n_in,
                              void* d_out, int out_size)
{
    const float* x = (const float*)d_in[0];
    float* out = (float*)d_out;
    dim3 grid(IMG / 32, IMG / 32, 16);   // (16,16,16) = 4096 CTAs
    diffjpeg_kernel<<<grid, 256>>>(x, out);
}

// round 15
// speedup vs baseline: 1.3091x; 1.0690x over previous
#include <cuda_runtime.h>
#include <cuda_bf16.h>

// ---------------------------------------------------------------------------
// DiffJPEG: out = x + (jpeg75(clip(x,0,1)) - x), x: [16,3,512,512] fp32
// Fused single kernel. CTA = 32x32 pixel tile, 256 threads, 5 CTAs/SM.
// R13: chroma 2x2 subsample fused into Phase A via shfl.xor (no stride-2
//      smem gather), pre-subsampled chroma arrays reused for reconstruction,
//      intra-group barriers demoted to __syncwarp (2 CTA barriers total).
// ---------------------------------------------------------------------------

// DCT-II matrix D[u][x] = 0.5*cos((2x+1)u*pi/16), row 0 scaled by 1/sqrt(2).
__constant__ float cD[64] = {
    0.3535533906f,  0.3535533906f,  0.3535533906f,  0.3535533906f,
    0.3535533906f,  0.3535533906f,  0.3535533906f,  0.3535533906f,
    0.4903926402f,  0.4157348062f,  0.2777851165f,  0.0975451610f,
   -0.0975451610f, -0.2777851165f, -0.4157348062f, -0.4903926402f,
    0.4619397663f,  0.1913417162f, -0.1913417162f, -0.4619397663f,
   -0.4619397663f, -0.1913417162f,  0.1913417162f,  0.4619397663f,
    0.4157348062f, -0.0975451610f, -0.4903926402f, -0.2777851165f,
    0.2777851165f,  0.4903926402f,  0.0975451610f, -0.4157348062f,
    0.3535533906f, -0.3535533906f, -0.3535533906f,  0.3535533906f,
    0.3535533906f, -0.3535533906f, -0.3535533906f,  0.3535533906f,
    0.2777851165f, -0.4903926402f,  0.0975451610f,  0.4157348062f,
   -0.4157348062f, -0.0975451610f,  0.4903926402f, -0.2777851165f,
    0.1913417162f, -0.4619397663f,  0.4619397663f, -0.1913417162f,
   -0.1913417162f,  0.4619397663f, -0.4619397663f,  0.1913417162f,
    0.0975451610f, -0.2777851165f,  0.4157348062f, -0.4903926402f,
    0.4903926402f, -0.4157348062f,  0.2777851165f, -0.0975451610f
};

// Quant tables pre-multiplied by factor = (200 - 2*75)/100 = 0.5 (exact in fp32)
__constant__ float cQY[64] = {
     8.0f,  5.5f,  5.0f,  8.0f, 12.0f, 20.0f, 25.5f, 30.5f,
     6.0f,  6.0f,  7.0f,  9.5f, 13.0f, 29.0f, 30.0f, 27.5f,
     7.0f,  6.5f,  8.0f, 12.0f, 20.0f, 28.5f, 34.5f, 28.0f,
     7.0f,  8.5f, 11.0f, 14.5f, 25.5f, 43.5f, 40.0f, 31.0f,
     9.0f, 11.0f, 18.5f, 28.0f, 34.0f, 54.5f, 51.5f, 38.5f,
    12.0f, 17.5f, 27.5f, 32.0f, 40.5f, 52.0f, 56.5f, 46.0f,
    24.5f, 32.0f, 39.0f, 43.5f, 51.5f, 60.5f, 60.0f, 50.5f,
    36.0f, 46.0f, 47.5f, 49.0f, 56.0f, 50.0f, 51.5f, 49.5f
};
__constant__ float cQC[64] = {
     8.5f,  9.0f, 12.0f, 23.5f, 49.5f, 49.5f, 49.5f, 49.5f,
     9.0f, 10.5f, 13.0f, 33.0f, 49.5f, 49.5f, 49.5f, 49.5f,
    12.0f, 13.0f, 28.0f, 49.5f, 49.5f, 49.5f, 49.5f, 49.5f,
    23.5f, 33.0f, 49.5f, 49.5f, 49.5f, 49.5f, 49.5f, 49.5f,
    49.5f, 49.5f, 49.5f, 49.5f, 49.5f, 49.5f, 49.5f, 49.5f,
    49.5f, 49.5f, 49.5f, 49.5f, 49.5f, 49.5f, 49.5f, 49.5f,
    49.5f, 49.5f, 49.5f, 49.5f, 49.5f, 49.5f, 49.5f, 49.5f,
    49.5f, 49.5f, 49.5f, 49.5f, 49.5f, 49.5f, 49.5f, 49.5f
};

#define IMG 512

__global__ void __launch_bounds__(256, 5)
diffjpeg_kernel(const float* __restrict__ in, float* __restrict__ out)
{
    __shared__ __align__(16) float sy  [32][36];  // Y: input then reconstructed
    __shared__ __align__(16) float scb2[16][20];  // subsampled Cb: in then rec
    __shared__ __align__(16) float scr2[16][20];  // subsampled Cr: in then rec
    __shared__ __align__(16) float st  [24][8][8]; // forward-transpose buffer T
    __shared__ __align__(16) float st2 [24][8][8]; // reconstructed-coef buffer S
    __shared__ float sD  [72];   // DCT matrix, stride 9 (lane-varying u reads)
    __shared__ float sQY [72];   // quant Y, stride 9
    __shared__ float sQC [72];   // quant C, stride 9

    const int t    = threadIdx.x;
    const int row  = t >> 3;          // 0..31
    const int col0 = (t & 7) << 2;    // 0,4,...,28

    const int b  = blockIdx.z;
    const int gy = blockIdx.y * 32 + row;
    const int gx = blockIdx.x * 32 + col0;

    const size_t plane = (size_t)IMG * IMG;
    const size_t base  = ((size_t)b * 3) * plane + (size_t)gy * IMG + gx;

    // ---------- Table copy to shared (stride 9) ----------
    if (t < 192) {
        int tab = t >> 6;             // 0: D, 1: QY, 2: QC
        int e   = t & 63;
        int dst = (e >> 3) * 9 + (e & 7);
        float v = (tab == 0) ? cD[e] : (tab == 1) ? cQY[e] : cQC[e];
        if (tab == 0)      sD [dst] = v;
        else if (tab == 1) sQY[dst] = v;
        else               sQC[dst] = v;
    }

    // ---------- Phase A: load, clip, *255, RGB->YCbCr, chroma 2x2 mean ----
    {
        const float4 xr4 = *(const float4*)(in + base);
        const float4 xg4 = *(const float4*)(in + base + plane);
        const float4 xb4 = *(const float4*)(in + base + 2 * plane);
        float xr[4] = {xr4.x, xr4.y, xr4.z, xr4.w};
        float xg[4] = {xg4.x, xg4.y, xg4.z, xg4.w};
        float xb[4] = {xb4.x, xb4.y, xb4.z, xb4.w};
        float ya[4], cba[4], cra[4];
        #pragma unroll
        for (int i = 0; i < 4; i++) {
            float R = fminf(fmaxf(xr[i], 0.f), 1.f) * 255.f;
            float G = fminf(fmaxf(xg[i], 0.f), 1.f) * 255.f;
            float B = fminf(fmaxf(xb[i], 0.f), 1.f) * 255.f;
            ya [i] =  0.299f    * R + 0.587f    * G + 0.114f    * B;
            cba[i] = -0.168736f * R - 0.331264f * G + 0.5f      * B + 128.f;
            cra[i] =  0.5f      * R - 0.418688f * G - 0.081312f * B + 128.f;
        }
        *(float4*)&sy[row][col0] = make_float4(ya[0], ya[1], ya[2], ya[3]);

        // Horizontal pair sums, then vertical partner via shfl.xor(8)
        float cbh0 = cba[0] + cba[1], cbh1 = cba[2] + cba[3];
        float crh0 = cra[0] + cra[1], crh1 = cra[2] + cra[3];
        float cbo0 = __shfl_xor_sync(0xffffffffu, cbh0, 8);
        float cbo1 = __shfl_xor_sync(0xffffffffu, cbh1, 8);
        float cro0 = __shfl_xor_sync(0xffffffffu, crh0, 8);
        float cro1 = __shfl_xor_sync(0xffffffffu, crh1, 8);
        if (!(row & 1)) {
            int r2 = row >> 1, c2 = col0 >> 1;
            *(float2*)&scb2[r2][c2] =
                make_float2(0.25f * (cbh0 + cbo0), 0.25f * (cbh1 + cbo1));
            *(float2*)&scr2[r2][c2] =
                make_float2(0.25f * (crh0 + cro0), 0.25f * (crh1 + cro1));
        }
    }
    __syncthreads();

    // 24 blocks: 0..15 Y (4x4 grid), 16..19 Cb (2x2), 20..23 Cr (2x2)
    const int bi = t >> 3;      // block id (valid for t < 192)
    const int r  = t & 7;       // row within block

    if (t < 192) {
        int br, bc;             // write-back coords

        // ---------- Phase B: row DCT  T[r][v] = sum_c X[r][c]*D[v][c] ----
        float xrow[8];
        if (bi < 16) {
            br = (bi >> 2) * 8 + r;
            bc = (bi & 3) * 8;
            const float4 lo = *(const float4*)&sy[br][bc];
            const float4 hi = *(const float4*)&sy[br][bc + 4];
            xrow[0] = lo.x - 128.f; xrow[1] = lo.y - 128.f;
            xrow[2] = lo.z - 128.f; xrow[3] = lo.w - 128.f;
            xrow[4] = hi.x - 128.f; xrow[5] = hi.y - 128.f;
            xrow[6] = hi.z - 128.f; xrow[7] = hi.w - 128.f;
        } else {
            const int cj = (bi < 20) ? (bi - 16) : (bi - 20);
            const float (*scs)[20] = (bi < 20) ? scb2 : scr2;
            br = (cj >> 1) * 8 + r;      // subsampled row
            bc = (cj & 1) * 8;           // subsampled col base
            const float4 lo = *(const float4*)&scs[br][bc];
            const float4 hi = *(const float4*)&scs[br][bc + 4];
            xrow[0] = lo.x - 128.f; xrow[1] = lo.y - 128.f;
            xrow[2] = lo.z - 128.f; xrow[3] = lo.w - 128.f;
            xrow[4] = hi.x - 128.f; xrow[5] = hi.y - 128.f;
            xrow[6] = hi.z - 128.f; xrow[7] = hi.w - 128.f;
        }
        float trow[8];
        #pragma unroll
        for (int v = 0; v < 8; v++) {
            float a = 0.f;
            #pragma unroll
            for (int c = 0; c < 8; c++) a += xrow[c] * cD[v * 8 + c];  // uniform -> LDC
            trow[v] = a;
        }
        *(float4*)&st[bi][r][0] = make_float4(trow[0], trow[1], trow[2], trow[3]);
        *(float4*)&st[bi][r][4] = make_float4(trow[4], trow[5], trow[6], trow[7]);

        __syncwarp();   // st[bi] is group-private; group lives in one warp

        // ---------- Phase C: column DCT + quantize + half inverse ----
        const int u = r;
        float dU[8];
        #pragma unroll
        for (int x = 0; x < 8; x++) dU[x] = sD[u * 9 + x];

        float k[8] = {0.f, 0.f, 0.f, 0.f, 0.f, 0.f, 0.f, 0.f};
        #pragma unroll
        for (int x = 0; x < 8; x++) {
            const float4 lo = *(const float4*)&st[bi][x][0];
            const float4 hi = *(const float4*)&st[bi][x][4];
            const float d = dU[x];
            k[0] += d * lo.x; k[1] += d * lo.y; k[2] += d * lo.z; k[3] += d * lo.w;
            k[4] += d * hi.x; k[5] += d * hi.y; k[6] += d * hi.z; k[7] += d * hi.w;
        }
        const float* qs = (bi < 16) ? sQY : sQC;
        #pragma unroll
        for (int v = 0; v < 8; v++) {
            float qq = qs[u * 9 + v];
            k[v] = rintf(k[v] / qq) * qq;         // round-half-even, true div
        }
        float srow[8];
        #pragma unroll
        for (int y = 0; y < 8; y++) {
            float a = 0.f;
            #pragma unroll
            for (int v = 0; v < 8; v++) a += k[v] * cD[v * 8 + y];
            srow[y] = a;
        }
        *(float4*)&st2[bi][r][0] = make_float4(srow[0], srow[1], srow[2], srow[3]);
        *(float4*)&st2[bi][r][4] = make_float4(srow[4], srow[5], srow[6], srow[7]);

        __syncwarp();   // st2[bi] group-private

        // ---------- Phase D: rec[r][y] = sum_u D[u][r]*S[u][y] + 128 ----
        float rec[8] = {0.f, 0.f, 0.f, 0.f, 0.f, 0.f, 0.f, 0.f};
        #pragma unroll
        for (int u2 = 0; u2 < 8; u2++) {
            const float d = sD[u2 * 9 + r];       // lane-varying, conflict-free
            const float4 lo = *(const float4*)&st2[bi][u2][0];
            const float4 hi = *(const float4*)&st2[bi][u2][4];
            rec[0] += d * lo.x; rec[1] += d * lo.y; rec[2] += d * lo.z; rec[3] += d * lo.w;
            rec[4] += d * hi.x; rec[5] += d * hi.y; rec[6] += d * hi.z; rec[7] += d * hi.w;
        }
        #pragma unroll
        for (int y = 0; y < 8; y++) rec[y] += 128.f;
        if (bi < 16) {
            *(float4*)&sy[br][bc]     = make_float4(rec[0], rec[1], rec[2], rec[3]);
            *(float4*)&sy[br][bc + 4] = make_float4(rec[4], rec[5], rec[6], rec[7]);
        } else if (bi < 20) {
            *(float4*)&scb2[br][bc]     = make_float4(rec[0], rec[1], rec[2], rec[3]);
            *(float4*)&scb2[br][bc + 4] = make_float4(rec[4], rec[5], rec[6], rec[7]);
        } else {
            *(float4*)&scr2[br][bc]     = make_float4(rec[0], rec[1], rec[2], rec[3]);
            *(float4*)&scr2[br][bc + 4] = make_float4(rec[4], rec[5], rec[6], rec[7]);
        }
    }
    __syncthreads();

    // ---------- Phase E: upsample chroma, YCbCr->RGB, clip, emit ----------
    // Re-load x (L1-resident from Phase A) instead of carrying 12 registers.
    {
        const float4 xr4 = *(const float4*)(in + base);
        const float4 xg4 = *(const float4*)(in + base + plane);
        const float4 xb4 = *(const float4*)(in + base + 2 * plane);
        const float xr[4] = {xr4.x, xr4.y, xr4.z, xr4.w};
        const float xg[4] = {xg4.x, xg4.y, xg4.z, xg4.w};
        const float xb[4] = {xb4.x, xb4.y, xb4.z, xb4.w};

        const float4 y4 = *(const float4*)&sy[row][col0];
        const float yv[4] = {y4.x, y4.y, y4.z, y4.w};

        float or_[4], og_[4], ob_[4];
        #pragma unroll
        for (int i = 0; i < 4; i++) {
            int cc = col0 + i;
            float Y   = yv[i];
            float cbm = scb2[row >> 1][cc >> 1] - 128.f;
            float crm = scr2[row >> 1][cc >> 1] - 128.f;
            float R2 = Y + 1.402f * crm;
            float G2 = Y - 0.344136f * cbm - 0.714136f * crm;
            float B2 = Y + 1.772f * cbm;
            R2 = fminf(fmaxf(R2, 0.f), 255.f) * (1.f / 255.f);
            G2 = fminf(fmaxf(G2, 0.f), 255.f) * (1.f / 255.f);
            B2 = fminf(fmaxf(B2, 0.f), 255.f) * (1.f / 255.f);
            // out = x + (jpeg - x), matching the reference's fp32 arithmetic
            or_[i] = xr[i] + (R2 - xr[i]);
            og_[i] = xg[i] + (G2 - xg[i]);
            ob_[i] = xb[i] + (B2 - xb[i]);
        }
        *(float4*)(out + base)             = make_float4(or_[0], or_[1], or_[2], or_[3]);
        *(float4*)(out + base + plane)     = make_float4(og_[0], og_[1], og_[2], og_[3]);
        *(float4*)(out + base + 2 * plane) = make_float4(ob_[0], ob_[1], ob_[2], ob_[3]);
    }
}

extern "C" void kernel_launch(void* const* d_in, const int* in_sizes, int n_in,
                              void* d_out, int out_size)
{
    const float* x = (const float*)d_in[0];
    float* out = (float*)d_out;
    dim3 grid(IMG / 32, IMG / 32, 16);   // (16,16,16) = 4096 CTAs
    diffjpeg_kernel<<<grid, 256>>>(x, out);
}